// round 1
// baseline (speedup 1.0000x reference)
#include <cuda_runtime.h>
#include <cuda_bf16.h>

// Problem constants
#define BB   8
#define CIN  64
#define HH   64
#define WW   64
#define KKT  9
#define OCH_OFF 1152          // 2*C*KK
#define OCH_MOD 576           // C*KK
#define OCH_TOT 1728
#define OC_FIN  128
#define MAXOFF  16.0f

// Scratch: combined offset(first 1152 ch, clipped) + mask(next 576 ch)
// layout g_om[b][r][y][x], r in [0,1728)
__device__ float g_om[(size_t)BB * OCH_TOT * HH * WW];   // 226.5 MB
// transposed final-conv weights: g_wt[ck][oc], ck in [0,576), oc in [0,128)
__device__ float g_wt[576 * 128];

// ---------------------------------------------------------------------------
// Kernel 1: fused 3x3 conv producing offset+mask channels.
// CTA tile: 64 out-channels x 64 pixels (one row y of one image b).
// 256 threads, each computes a 4x4 micro-tile.
// ---------------------------------------------------------------------------
__global__ __launch_bounds__(256) void conv_om_kernel(
    const float* __restrict__ x,
    const float* __restrict__ w_off,
    const float* __restrict__ b_off,
    const float* __restrict__ w_mod,
    const float* __restrict__ b_mod)
{
    const int ocBlk = blockIdx.x;           // 0..26
    const int y     = blockIdx.y;           // 0..63
    const int b     = blockIdx.z;           // 0..7
    const int ocBase = ocBlk * 64;
    const int tid = threadIdx.x;
    const int tx  = tid & 15;               // pixel group
    const int ty  = tid >> 4;               // oc group
    const int px0  = tx * 4;
    const int ocL0 = ty * 4;

    __shared__ float xs[3][68];             // 3 input rows, halo-padded cols
    __shared__ float ws[64 * 9];            // weights for 64 oc, current c

    float acc[4][4];
#pragma unroll
    for (int i = 0; i < 4; i++)
#pragma unroll
        for (int j = 0; j < 4; j++) acc[i][j] = 0.f;

    for (int c = 0; c < CIN; c++) {
        // cooperative load of 3 halo-padded x rows for channel c
        for (int idx = tid; idx < 3 * 66; idx += 256) {
            int r = idx / 66, j = idx % 66;
            int yy = y + r - 1;
            float v = 0.f;
            if (j >= 1 && j <= 64 && yy >= 0 && yy < HH)
                v = __ldg(&x[(((size_t)b * CIN + c) * HH + yy) * WW + (j - 1)]);
            xs[r][j] = v;
        }
        // cooperative load of weights: 64 oc x 9 taps for channel c
        for (int idx = tid; idx < 576; idx += 256) {
            int ocl = idx / 9, t = idx % 9;
            int r = ocBase + ocl;
            float wv;
            if (r < OCH_OFF) wv = __ldg(&w_off[((size_t)r * CIN + c) * 9 + t]);
            else             wv = __ldg(&w_mod[((size_t)(r - OCH_OFF) * CIN + c) * 9 + t]);
            ws[idx] = wv;
        }
        __syncthreads();

#pragma unroll
        for (int ki = 0; ki < 3; ki++) {
            float xr[6];
#pragma unroll
            for (int j = 0; j < 6; j++) xr[j] = xs[ki][px0 + j];
#pragma unroll
            for (int kj = 0; kj < 3; kj++) {
                float wv[4];
#pragma unroll
                for (int i = 0; i < 4; i++) wv[i] = ws[(ocL0 + i) * 9 + ki * 3 + kj];
#pragma unroll
                for (int i = 0; i < 4; i++)
#pragma unroll
                    for (int j = 0; j < 4; j++)
                        acc[i][j] = fmaf(wv[i], xr[j + kj], acc[i][j]);
            }
        }
        __syncthreads();
    }

    // epilogue: bias + clip (offset channels only), store to scratch
#pragma unroll
    for (int i = 0; i < 4; i++) {
        int r = ocBase + ocL0 + i;
        float bias = (r < OCH_OFF) ? __ldg(&b_off[r]) : __ldg(&b_mod[r - OCH_OFF]);
#pragma unroll
        for (int j = 0; j < 4; j++) {
            float v = acc[i][j] + bias;
            if (r < OCH_OFF) v = fminf(fmaxf(v, -MAXOFF), MAXOFF);
            g_om[(((size_t)b * OCH_TOT + r) * HH + y) * WW + (px0 + j)] = v;
        }
    }
}

// ---------------------------------------------------------------------------
// Kernel 2: transpose w_conv [128][576] -> g_wt [576][128]
// ---------------------------------------------------------------------------
__global__ void transpose_wconv(const float* __restrict__ w_conv)
{
    int i = blockIdx.x * 256 + threadIdx.x;
    if (i < OC_FIN * 576) {
        int oc = i / 576, ck = i % 576;
        g_wt[ck * 128 + oc] = w_conv[i];
    }
}

// ---------------------------------------------------------------------------
// Kernel 3: deformable bilinear sampling + final GEMM.
// CTA = one (b, y) row: 64 pixels x 128 out channels.
// 256 threads; channel-chunked (4 channels = 36 ck columns per chunk).
// ---------------------------------------------------------------------------
__global__ __launch_bounds__(256) void deform_gemm_kernel(
    const float* __restrict__ x,
    float* __restrict__ out)
{
    const int y = blockIdx.x;               // 0..63
    const int b = blockIdx.y;               // 0..7
    const int tid = threadIdx.x;
    const int tx = tid & 15;
    const int ty = tid >> 4;
    const int px0 = tx * 4;
    const int oc0 = ty * 8;

    __shared__ float ss[4 * 9 * 64];        // [cc][k][px]  (9216 B)
    __shared__ float wcs[36][128];          // [ck][oc]     (18432 B)

    float acc[8][4];
#pragma unroll
    for (int i = 0; i < 8; i++)
#pragma unroll
        for (int j = 0; j < 4; j++) acc[i][j] = 0.f;

    const float* xb  = x + (size_t)b * CIN * HH * WW;
    const float* omb = g_om + (size_t)b * OCH_TOT * HH * WW;

    for (int c0 = 0; c0 < CIN; c0 += 4) {
        // load w_conv chunk (transposed, coalesced): 36 ck x 128 oc
        for (int idx = tid; idx < 36 * 128; idx += 256) {
            ((float*)wcs)[idx] = g_wt[(c0 * 9 + (idx >> 7)) * 128 + (idx & 127)];
        }
        // compute samples for 4 channels x 9 taps x 64 pixels
        for (int s = tid; s < 4 * 9 * 64; s += 256) {
            int px = s & 63;
            int k  = (s >> 6) % 9;
            int cc = s / 576;
            int c  = c0 + cc;
            int ki = k / 3, kj = k % 3;
            float dy = omb[(((size_t)c * 18 + k * 2 + 0) * HH + y) * WW + px];
            float dx = omb[(((size_t)c * 18 + k * 2 + 1) * HH + y) * WW + px];
            float m  = omb[(((size_t)OCH_OFF + c * 9 + k) * HH + y) * WW + px];
            float py  = dy + (float)(y - 1 + ki);
            float pxf = dx + (float)(px - 1 + kj);
            float v = 0.f;
            if (py > -1.f && py < (float)HH && pxf > -1.f && pxf < (float)WW) {
                float y0f = floorf(py), x0f = floorf(pxf);
                int y0 = (int)y0f, x0 = (int)x0f;
                float wy = py - y0f, wx = pxf - x0f;
                const float* xc = xb + (size_t)c * HH * WW;
                float v00 = 0.f, v01 = 0.f, v10 = 0.f, v11 = 0.f;
                bool y0i = (y0 >= 0) & (y0 < HH);
                bool y1i = (y0 + 1 >= 0) & (y0 + 1 < HH);
                bool x0i = (x0 >= 0) & (x0 < WW);
                bool x1i = (x0 + 1 >= 0) & (x0 + 1 < WW);
                if (y0i & x0i) v00 = __ldg(&xc[y0 * WW + x0]);
                if (y0i & x1i) v01 = __ldg(&xc[y0 * WW + x0 + 1]);
                if (y1i & x0i) v10 = __ldg(&xc[(y0 + 1) * WW + x0]);
                if (y1i & x1i) v11 = __ldg(&xc[(y0 + 1) * WW + x0 + 1]);
                v = (1.f - wy) * ((1.f - wx) * v00 + wx * v01)
                  +        wy  * ((1.f - wx) * v10 + wx * v11);
            }
            ss[s] = v * m;
        }
        __syncthreads();

        // GEMM over this chunk's 36 ck columns
#pragma unroll
        for (int ck = 0; ck < 36; ck++) {
            float4 sv4 = *(const float4*)&ss[ck * 64 + px0];
            float sv[4] = {sv4.x, sv4.y, sv4.z, sv4.w};
            float4 w0 = *(const float4*)&wcs[ck][oc0];
            float4 w1 = *(const float4*)&wcs[ck][oc0 + 4];
            float wv[8] = {w0.x, w0.y, w0.z, w0.w, w1.x, w1.y, w1.z, w1.w};
#pragma unroll
            for (int i = 0; i < 8; i++)
#pragma unroll
                for (int j = 0; j < 4; j++)
                    acc[i][j] = fmaf(wv[i], sv[j], acc[i][j]);
        }
        __syncthreads();
    }

    // write out[b][oc][y][px]
#pragma unroll
    for (int i = 0; i < 8; i++)
#pragma unroll
        for (int j = 0; j < 4; j++)
            out[(((size_t)b * OC_FIN + (oc0 + i)) * HH + y) * WW + (px0 + j)] = acc[i][j];
}

// ---------------------------------------------------------------------------
extern "C" void kernel_launch(void* const* d_in, const int* in_sizes, int n_in,
                              void* d_out, int out_size)
{
    const float* x      = (const float*)d_in[0];
    const float* w_off  = (const float*)d_in[1];
    const float* b_off  = (const float*)d_in[2];
    const float* w_mod  = (const float*)d_in[3];
    const float* b_mod  = (const float*)d_in[4];
    const float* w_conv = (const float*)d_in[5];
    float* out = (float*)d_out;

    dim3 g1(OCH_TOT / 64, HH, BB);          // 27 x 64 x 8
    conv_om_kernel<<<g1, 256>>>(x, w_off, b_off, w_mod, b_mod);

    transpose_wconv<<<(OC_FIN * 576 + 255) / 256, 256>>>(w_conv);

    dim3 g3(HH, BB);                        // 64 x 8
    deform_gemm_kernel<<<g3, 256>>>(x, out);
}